// round 1
// baseline (speedup 1.0000x reference)
#include <cuda_runtime.h>
#include <cuda_bf16.h>
#include <math.h>

#define BB 8
#define SS 2048
#define DIMV 240
#define NTOK (BB*SS)          // 16384
#define NEXP 8
#define NDEPTH 8
#define LATENTV 8
#define LOWD 80               // DIM / TRIALITY
#define LNEPS 1e-5f

// ------------------------- device scratch (no cudaMalloc allowed) ----------
__device__ float g_h[(size_t)NTOK * DIMV];          // current hidden state
__device__ float g_part[2][(size_t)NTOK * DIMV];    // per-slot expert partials
__device__ int   g_cnt[NEXP];
__device__ int   g_list_tok[NEXP][NTOK];
__device__ float g_list_w[NEXP][NTOK];
__device__ int   g_list_k[NEXP][NTOK];
__device__ int   g_route_e[NTOK * 2];
__device__ float g_route_w[NTOK * 2];

// ------------------------- cycle block -------------------------------------
// h[d] = (x1[d] + x1[d-1]*sin(emb[d]) + x1[d-2]*sin(emb[d-1])*cos(emb[d])) / 3
// x1[d] = x[d]*(cos(emb[d]) + pump);  emb[s,d] = (roots[s%240] @ proj_W)[d%80]
__global__ void cycle_kernel(const float* __restrict__ x,
                             const int* __restrict__ step,
                             const float* __restrict__ roots,
                             const float* __restrict__ projW) {
    __shared__ float s_emb[DIMV];
    __shared__ float s_x1[DIMV];
    int t = blockIdx.x;          // token
    int d = threadIdx.x;         // 0..239
    int s = t % SS;
    int r = s % 240;
    int j = d % LOWD;
    float emb = 0.f;
#pragma unroll
    for (int i = 0; i < LATENTV; i++)
        emb += roots[r * LATENTV + i] * projW[i * LOWD + j];
    s_emb[d] = emb;

    float pump = 0.8f * sinf((float)(*step) * 0.006f * 2.0f * 3.14159265358979323846f);
    float xv = x[(size_t)t * DIMV + d];
    float x1 = xv * (cosf(emb) + pump);
    s_x1[d] = x1;
    __syncthreads();

    int dm1 = (d + DIMV - 1) % DIMV;
    int dm2 = (d + DIMV - 2) % DIMV;
    float h = (s_x1[d]
             + s_x1[dm1] * sinf(s_emb[d])
             + s_x1[dm2] * sinf(s_emb[dm1]) * cosf(s_emb[d])) * (1.0f / 3.0f);
    g_h[(size_t)t * DIMV + d] = h;
}

// ------------------------- per-layer: zero counters ------------------------
__global__ void zero_cnt_kernel() {
    if (threadIdx.x < NEXP) g_cnt[threadIdx.x] = 0;
}

// ------------------------- per-layer: gating + routing ---------------------
// 8 threads per token, one expert logit each; top-2 w/ first-index tie-break.
__global__ void gate_kernel(const float* __restrict__ gW,   // [240, 8]
                            const float* __restrict__ gb) { // [8]
    int tid  = threadIdx.x;
    int tok  = blockIdx.x * 32 + (tid >> 3);
    int e    = tid & 7;
    const float* h = g_h + (size_t)tok * DIMV;

    float acc = 0.f;
#pragma unroll 8
    for (int d = 0; d < DIMV; d++)
        acc += h[d] * gW[d * NEXP + e];
    acc += gb[e];

    int lane = tid & 31;
    int baselane = lane & ~7;    // leader lane of the 8-lane group
    float l[8];
#pragma unroll
    for (int q = 0; q < 8; q++)
        l[q] = __shfl_sync(0xffffffffu, acc, baselane + q);

    if (e == 0) {
        int e0 = 0; float b0 = l[0];
#pragma unroll
        for (int q = 1; q < 8; q++)
            if (l[q] > b0) { b0 = l[q]; e0 = q; }
        int e1 = -1; float b1 = -1e30f;
#pragma unroll
        for (int q = 0; q < 8; q++)
            if (q != e0 && l[q] > b1) { b1 = l[q]; e1 = q; }

        float w0 = 1.0f / (1.0f + expf(b1 - b0));
        float w1 = 1.0f - w0;

        int p0 = atomicAdd(&g_cnt[e0], 1);
        g_list_tok[e0][p0] = tok; g_list_w[e0][p0] = w0; g_list_k[e0][p0] = 0;
        int p1 = atomicAdd(&g_cnt[e1], 1);
        g_list_tok[e1][p1] = tok; g_list_w[e1][p1] = w1; g_list_k[e1][p1] = 1;

        g_route_e[tok * 2 + 0] = e0; g_route_e[tok * 2 + 1] = e1;
        g_route_w[tok * 2 + 0] = w0; g_route_w[tok * 2 + 1] = w1;
    }
}

// ------------------------- per-layer: grouped expert GEMM ------------------
// Block = (64 tokens of expert e) x (N=240). Writes w * (h @ eW[e]) into
// g_part[slot]. Each (slot, token, f) written exactly once per layer.
#define MT 64
__global__ __launch_bounds__(256, 2)
void moe_gemm_kernel(const float* __restrict__ eW) { // [E, 240, 240]
    int e = blockIdx.y;
    int cnt = g_cnt[e];
    int base = blockIdx.x * MT;
    if (base >= cnt) return;
    int mr = min(MT, cnt - base);

    __shared__ float As[MT][17];       // 16 K-slice + pad
    __shared__ float Bs[16][DIMV];
    __shared__ int   s_tok[MT];
    __shared__ float s_w[MT];
    __shared__ int   s_k[MT];

    int tid = threadIdx.x;             // 256
    if (tid < MT) {
        if (tid < mr) {
            s_tok[tid] = g_list_tok[e][base + tid];
            s_w[tid]   = g_list_w[e][base + tid];
            s_k[tid]   = g_list_k[e][base + tid];
        } else {
            s_tok[tid] = 0; s_w[tid] = 0.f; s_k[tid] = 0;
        }
    }
    __syncthreads();

    int tx = tid & 15;                 // column group
    int ty = tid >> 4;                 // row group
    float acc[4][15];
#pragma unroll
    for (int i = 0; i < 4; i++)
#pragma unroll
        for (int jq = 0; jq < 15; jq++) acc[i][jq] = 0.f;

    const float* W = eW + (size_t)e * DIMV * DIMV;

    for (int k0 = 0; k0 < DIMV; k0 += 16) {
        // gather A slice: 64 x 16
        for (int i = tid; i < MT * 16; i += 256) {
            int rr = i >> 4, cc = i & 15;
            As[rr][cc] = (rr < mr) ? g_h[(size_t)s_tok[rr] * DIMV + k0 + cc] : 0.f;
        }
        // load B slice: 16 x 240
        for (int i = tid; i < 16 * DIMV; i += 256) {
            int rr = i / DIMV, cc = i - rr * DIMV;
            Bs[rr][cc] = W[(size_t)(k0 + rr) * DIMV + cc];
        }
        __syncthreads();
#pragma unroll
        for (int dk = 0; dk < 16; dk++) {
            float a[4], b[15];
#pragma unroll
            for (int i = 0; i < 4; i++) a[i] = As[ty * 4 + i][dk];
#pragma unroll
            for (int jq = 0; jq < 15; jq++) b[jq] = Bs[dk][tx + 16 * jq];
#pragma unroll
            for (int i = 0; i < 4; i++)
#pragma unroll
                for (int jq = 0; jq < 15; jq++)
                    acc[i][jq] += a[i] * b[jq];
        }
        __syncthreads();
    }

#pragma unroll
    for (int i = 0; i < 4; i++) {
        int rr = ty * 4 + i;
        if (rr < mr) {
            float w = s_w[rr];
            float* dst = &g_part[s_k[rr]][(size_t)s_tok[rr] * DIMV];
#pragma unroll
            for (int jq = 0; jq < 15; jq++)
                dst[tx + 16 * jq] = w * acc[i][jq];
        }
    }
}

// ------------------------- per-layer: epilogue (bias + h = out + LN(out)) --
__global__ void epi_kernel(const float* __restrict__ eb,     // [E, 240]
                           const float* __restrict__ gamma,
                           const float* __restrict__ beta) {
    int warp = threadIdx.x >> 5;
    int lane = threadIdx.x & 31;
    int tok  = blockIdx.x * 8 + warp;

    int   e0 = g_route_e[tok * 2 + 0], e1 = g_route_e[tok * 2 + 1];
    float w0 = g_route_w[tok * 2 + 0], w1 = g_route_w[tok * 2 + 1];

    const float* p0 = &g_part[0][(size_t)tok * DIMV];
    const float* p1 = &g_part[1][(size_t)tok * DIMV];

    float v[8];
    float sum = 0.f;
#pragma unroll
    for (int jq = 0; jq < 8; jq++) {
        int d = lane + 32 * jq;
        if (d < DIMV) {
            v[jq] = p0[d] + p1[d] + w0 * eb[e0 * DIMV + d] + w1 * eb[e1 * DIMV + d];
            sum += v[jq];
        } else v[jq] = 0.f;
    }
#pragma unroll
    for (int o = 16; o > 0; o >>= 1) sum += __shfl_xor_sync(0xffffffffu, sum, o);
    float mean = sum * (1.0f / DIMV);

    float vs = 0.f;
#pragma unroll
    for (int jq = 0; jq < 8; jq++) {
        int d = lane + 32 * jq;
        if (d < DIMV) { float c = v[jq] - mean; vs += c * c; }
    }
#pragma unroll
    for (int o = 16; o > 0; o >>= 1) vs += __shfl_xor_sync(0xffffffffu, vs, o);
    float inv = 1.0f / sqrtf(vs * (1.0f / DIMV) + LNEPS);

#pragma unroll
    for (int jq = 0; jq < 8; jq++) {
        int d = lane + 32 * jq;
        if (d < DIMV) {
            float ln = (v[jq] - mean) * inv * gamma[d] + beta[d];
            g_h[(size_t)tok * DIMV + d] = v[jq] + ln;
        }
    }
}

// ------------------------- head: mean over S, dot, sigmoid -----------------
__global__ void head_kernel(const float* __restrict__ hW,   // [240]
                            const float* __restrict__ hb,   // [1]
                            float* __restrict__ out) {      // [B]
    int b = blockIdx.x;
    int tid = threadIdx.x;       // 256
    const float* hp = g_h + (size_t)b * SS * DIMV;
    float acc = 0.f;
    for (int i = tid; i < SS * DIMV; i += 256)
        acc += hp[i] * hW[i % DIMV];
    __shared__ float red[256];
    red[tid] = acc;
    __syncthreads();
    for (int s2 = 128; s2 > 0; s2 >>= 1) {
        if (tid < s2) red[tid] += red[tid + s2];
        __syncthreads();
    }
    if (tid == 0) {
        float z = red[0] * (1.0f / SS) + hb[0];
        out[b] = 1.0f / (1.0f + expf(-z));
    }
}

// ------------------------- launch ------------------------------------------
extern "C" void kernel_launch(void* const* d_in, const int* in_sizes, int n_in,
                              void* d_out, int out_size) {
    const float* x     = (const float*)d_in[0];
    const int*   step  = (const int*)  d_in[1];
    const float* roots = (const float*)d_in[2];
    const float* projW = (const float*)d_in[3];
    const float* gW    = (const float*)d_in[4];
    const float* gb    = (const float*)d_in[5];
    const float* eW    = (const float*)d_in[6];
    const float* ebias = (const float*)d_in[7];
    const float* gamma = (const float*)d_in[8];
    const float* beta  = (const float*)d_in[9];
    const float* hW    = (const float*)d_in[10];
    const float* hb    = (const float*)d_in[11];
    float* out = (float*)d_out;

    cycle_kernel<<<NTOK, DIMV>>>(x, step, roots, projW);

    for (int L = 0; L < NDEPTH; L++) {
        zero_cnt_kernel<<<1, 32>>>();
        gate_kernel<<<NTOK / 32, 256>>>(gW + (size_t)L * DIMV * NEXP,
                                        gb + (size_t)L * NEXP);
        dim3 gg(NTOK / MT, NEXP);
        moe_gemm_kernel<<<gg, 256>>>(eW + (size_t)L * NEXP * DIMV * DIMV);
        epi_kernel<<<NTOK / 8, 256>>>(ebias + (size_t)L * NEXP * DIMV, gamma, beta);
    }

    head_kernel<<<BB, 256>>>(hW, hb, out);
}

// round 2
// speedup vs baseline: 1.2898x; 1.2898x over previous
#include <cuda_runtime.h>
#include <cuda_bf16.h>
#include <math.h>

#define BB 8
#define SS 2048
#define DIMV 240
#define NTOK (BB*SS)          // 16384
#define NEXP 8
#define NDEPTH 8
#define LATENTV 8
#define LOWD 80               // DIM / TRIALITY
#define LNEPS 1e-5f
#define PI_F 3.14159265358979323846f

// ------------------------- device scratch ----------------------------------
__device__ float g_h[(size_t)NTOK * DIMV];          // current hidden state
__device__ float g_part[2][(size_t)NTOK * DIMV];    // per-slot expert partials
__device__ int   g_cnt[NDEPTH][NEXP];
__device__ int   g_list_tok[NEXP][NTOK];
__device__ float g_list_w[NEXP][NTOK];
__device__ int   g_list_k[NEXP][NTOK];
__device__ int   g_route_e[NTOK * 2];
__device__ float g_route_w[NTOK * 2];
__device__ float g_ce[240 * DIMV];                  // cos(emb) per (s%240, d)
__device__ float g_se[240 * DIMV];                  // sin(emb) per (s%240, d)

// ------------------------- f32x2 helpers ------------------------------------
__device__ __forceinline__ void fma2(unsigned long long &d,
                                     unsigned long long a,
                                     unsigned long long b) {
    asm("fma.rn.f32x2 %0, %1, %2, %0;" : "+l"(d) : "l"(a), "l"(b));
}
__device__ __forceinline__ unsigned long long pack2(float a) {
    unsigned long long r;
    asm("mov.b64 %0, {%1, %1};" : "=l"(r) : "f"(a));
    return r;
}
__device__ __forceinline__ void unpack2(unsigned long long v, float &lo, float &hi) {
    asm("mov.b64 {%0, %1}, %2;" : "=f"(lo), "=f"(hi) : "l"(v));
}

// ------------------------- setup: emb tables + counter zero -----------------
__global__ void setup_kernel(const float* __restrict__ roots,
                             const float* __restrict__ projW) {
    int s = blockIdx.x;          // 0..239
    int d = threadIdx.x;         // 0..239
    int j = d % LOWD;
    float emb = 0.f;
#pragma unroll
    for (int i = 0; i < LATENTV; i++)
        emb += roots[s * LATENTV + i] * projW[i * LOWD + j];
    g_ce[s * DIMV + d] = cosf(emb);
    g_se[s * DIMV + d] = sinf(emb);
    if (blockIdx.x == 0 && d < NDEPTH * NEXP)
        ((int*)g_cnt)[d] = 0;
}

// ------------------------- cycle block --------------------------------------
__global__ void cycle_kernel(const float* __restrict__ x,
                             const int* __restrict__ step) {
    __shared__ float s_x1[DIMV];
    __shared__ float s_se[DIMV];
    __shared__ float s_pump;
    int t = blockIdx.x;
    int d = threadIdx.x;
    int r = (t % SS) % 240;
    if (d == 0) s_pump = 0.8f * sinf((float)(*step) * 0.006f * 2.0f * PI_F);
    float ce = g_ce[r * DIMV + d];
    float se = g_se[r * DIMV + d];
    s_se[d] = se;
    __syncthreads();
    float x1 = x[(size_t)t * DIMV + d] * (ce + s_pump);
    s_x1[d] = x1;
    __syncthreads();
    int dm1 = (d + DIMV - 1) % DIMV;
    int dm2 = (d + DIMV - 2) % DIMV;
    float h = (s_x1[d]
             + s_x1[dm1] * se
             + s_x1[dm2] * s_se[dm1] * ce) * (1.0f / 3.0f);
    g_h[(size_t)t * DIMV + d] = h;
}

// ------------------------- gating: warp per token ---------------------------
__global__ void gate_kernel(const float* __restrict__ gW,   // [240, 8]
                            const float* __restrict__ gb,   // [8]
                            int L) {
    int warp = threadIdx.x >> 5;
    int lane = threadIdx.x & 31;
    int tok  = blockIdx.x * 8 + warp;
    const float* h = g_h + (size_t)tok * DIMV;

    float acc[8];
#pragma unroll
    for (int e = 0; e < 8; e++) acc[e] = 0.f;

#pragma unroll
    for (int it = 0; it < 8; it++) {
        int d = lane + 32 * it;
        if (d < DIMV) {
            float hv = h[d];
            float4 w0 = *(const float4*)&gW[d * 8];
            float4 w1 = *(const float4*)&gW[d * 8 + 4];
            acc[0] += hv * w0.x; acc[1] += hv * w0.y;
            acc[2] += hv * w0.z; acc[3] += hv * w0.w;
            acc[4] += hv * w1.x; acc[5] += hv * w1.y;
            acc[6] += hv * w1.z; acc[7] += hv * w1.w;
        }
    }
#pragma unroll
    for (int e = 0; e < 8; e++)
#pragma unroll
        for (int o = 16; o > 0; o >>= 1)
            acc[e] += __shfl_xor_sync(0xffffffffu, acc[e], o);

    if (lane == 0) {
        float l[8];
#pragma unroll
        for (int e = 0; e < 8; e++) l[e] = acc[e] + gb[e];
        int e0 = 0; float b0 = l[0];
#pragma unroll
        for (int q = 1; q < 8; q++)
            if (l[q] > b0) { b0 = l[q]; e0 = q; }
        int e1 = -1; float b1 = -1e30f;
#pragma unroll
        for (int q = 0; q < 8; q++)
            if (q != e0 && l[q] > b1) { b1 = l[q]; e1 = q; }

        float w0 = 1.0f / (1.0f + expf(b1 - b0));
        float w1 = 1.0f - w0;

        int p0 = atomicAdd(&g_cnt[L][e0], 1);
        g_list_tok[e0][p0] = tok; g_list_w[e0][p0] = w0; g_list_k[e0][p0] = 0;
        int p1 = atomicAdd(&g_cnt[L][e1], 1);
        g_list_tok[e1][p1] = tok; g_list_w[e1][p1] = w1; g_list_k[e1][p1] = 1;

        g_route_e[tok * 2 + 0] = e0; g_route_e[tok * 2 + 1] = e1;
        g_route_w[tok * 2 + 0] = w0; g_route_w[tok * 2 + 1] = w1;
    }
}

// ------------------------- grouped expert GEMM (f32x2) ----------------------
// Block = 64 gathered tokens x 256 cols (240 real + 16 pad). 256 threads,
// thread tile 4 rows x 8 col-pairs, packed fma.rn.f32x2 accumulation.
#define MT 64
__global__ __launch_bounds__(256, 2)
void moe_gemm_kernel(const float* __restrict__ eW, int L) { // [E, 240, 240]
    int e = blockIdx.y;
    int cnt = g_cnt[L][e];
    int base = blockIdx.x * MT;
    if (base >= cnt) return;
    int mr = min(MT, cnt - base);

    __shared__ __align__(16) float As_t[16][68];   // [k][token], padded rows
    __shared__ __align__(16) float Bs[16][256];    // [k][col], cols 240..255 pad
    __shared__ int   s_tok[MT];
    __shared__ float s_w[MT];
    __shared__ int   s_k[MT];

    int tid = threadIdx.x;             // 256
    if (tid < MT) {
        if (tid < mr) {
            s_tok[tid] = g_list_tok[e][base + tid];
            s_w[tid]   = g_list_w[e][base + tid];
            s_k[tid]   = g_list_k[e][base + tid];
        } else {
            s_tok[tid] = 0; s_w[tid] = 0.f; s_k[tid] = 0;
        }
    }
    // zero the pad columns once (never overwritten by data loads)
    {
        int rr = tid >> 4, cc = tid & 15;           // 256 threads cover 16x16
        Bs[rr][240 + cc] = 0.f;
    }
    __syncthreads();

    int tx = tid & 15;                 // col-pair group 0..15
    int ty = tid >> 4;                 // row group 0..15

    unsigned long long acc[4][8];
#pragma unroll
    for (int i = 0; i < 4; i++)
#pragma unroll
        for (int jq = 0; jq < 8; jq++) acc[i][jq] = 0ull;

    const float* W = eW + (size_t)e * DIMV * DIMV;

    for (int k0 = 0; k0 < DIMV; k0 += 16) {
        // gather A slice 64x16 -> transposed As_t[k][token]
        {
            int rr = tid >> 2;         // token row 0..63
            int c4 = tid & 3;          // which float4 of the 16 k's
            float4 v;
            if (rr < mr)
                v = *(const float4*)&g_h[(size_t)s_tok[rr] * DIMV + k0 + c4 * 4];
            else
                v = make_float4(0.f, 0.f, 0.f, 0.f);
            As_t[c4 * 4 + 0][rr] = v.x;
            As_t[c4 * 4 + 1][rr] = v.y;
            As_t[c4 * 4 + 2][rr] = v.z;
            As_t[c4 * 4 + 3][rr] = v.w;
        }
        // load B slice 16x240 via float4
        for (int i = tid; i < 16 * 60; i += 256) {
            int rr = i / 60, cc = i - rr * 60;
            *(float4*)&Bs[rr][cc * 4] =
                *(const float4*)&W[(size_t)(k0 + rr) * DIMV + cc * 4];
        }
        __syncthreads();

#pragma unroll
        for (int dk = 0; dk < 16; dk++) {
            float4 av = *(const float4*)&As_t[dk][ty * 4];
            unsigned long long a2[4];
            a2[0] = pack2(av.x); a2[1] = pack2(av.y);
            a2[2] = pack2(av.z); a2[3] = pack2(av.w);
            unsigned long long bv[8];
#pragma unroll
            for (int jq = 0; jq < 8; jq++)
                bv[jq] = *(const unsigned long long*)&Bs[dk][(tx + 16 * jq) * 2];
#pragma unroll
            for (int i = 0; i < 4; i++)
#pragma unroll
                for (int jq = 0; jq < 8; jq++)
                    fma2(acc[i][jq], a2[i], bv[jq]);
        }
        __syncthreads();
    }

#pragma unroll
    for (int i = 0; i < 4; i++) {
        int rr = ty * 4 + i;
        if (rr < mr) {
            float w = s_w[rr];
            float* dst = &g_part[s_k[rr]][(size_t)s_tok[rr] * DIMV];
#pragma unroll
            for (int jq = 0; jq < 8; jq++) {
                int P = tx + 16 * jq;
                if (P < 120) {
                    float lo, hi;
                    unpack2(acc[i][jq], lo, hi);
                    float2 o; o.x = w * lo; o.y = w * hi;
                    *(float2*)&dst[2 * P] = o;
                }
            }
        }
    }
}

// ------------------------- epilogue: bias + h = out + LN(out) ---------------
__global__ void epi_kernel(const float* __restrict__ eb,     // [E, 240]
                           const float* __restrict__ gamma,
                           const float* __restrict__ beta) {
    int warp = threadIdx.x >> 5;
    int lane = threadIdx.x & 31;
    int tok  = blockIdx.x * 8 + warp;

    int   e0 = g_route_e[tok * 2 + 0], e1 = g_route_e[tok * 2 + 1];
    float w0 = g_route_w[tok * 2 + 0], w1 = g_route_w[tok * 2 + 1];

    const float* p0 = &g_part[0][(size_t)tok * DIMV];
    const float* p1 = &g_part[1][(size_t)tok * DIMV];

    float v[8];
    float sum = 0.f;
#pragma unroll
    for (int jq = 0; jq < 8; jq++) {
        int d = lane + 32 * jq;
        if (d < DIMV) {
            v[jq] = p0[d] + p1[d] + w0 * eb[e0 * DIMV + d] + w1 * eb[e1 * DIMV + d];
            sum += v[jq];
        } else v[jq] = 0.f;
    }
#pragma unroll
    for (int o = 16; o > 0; o >>= 1) sum += __shfl_xor_sync(0xffffffffu, sum, o);
    float mean = sum * (1.0f / DIMV);

    float vs = 0.f;
#pragma unroll
    for (int jq = 0; jq < 8; jq++) {
        int d = lane + 32 * jq;
        if (d < DIMV) { float c = v[jq] - mean; vs += c * c; }
    }
#pragma unroll
    for (int o = 16; o > 0; o >>= 1) vs += __shfl_xor_sync(0xffffffffu, vs, o);
    float inv = 1.0f / sqrtf(vs * (1.0f / DIMV) + LNEPS);

#pragma unroll
    for (int jq = 0; jq < 8; jq++) {
        int d = lane + 32 * jq;
        if (d < DIMV) {
            float ln = (v[jq] - mean) * inv * gamma[d] + beta[d];
            g_h[(size_t)tok * DIMV + d] = v[jq] + ln;
        }
    }
}

// ------------------------- head ---------------------------------------------
__global__ void head_kernel(const float* __restrict__ hW,   // [240]
                            const float* __restrict__ hb,   // [1]
                            float* __restrict__ out) {      // [B]
    int b = blockIdx.x;
    int tid = threadIdx.x;       // 256
    const float* hp = g_h + (size_t)b * SS * DIMV;
    float acc = 0.f;
    for (int i = tid; i < SS * DIMV; i += 256)
        acc += hp[i] * hW[i % DIMV];
    __shared__ float red[256];
    red[tid] = acc;
    __syncthreads();
    for (int s2 = 128; s2 > 0; s2 >>= 1) {
        if (tid < s2) red[tid] += red[tid + s2];
        __syncthreads();
    }
    if (tid == 0) {
        float z = red[0] * (1.0f / SS) + hb[0];
        out[b] = 1.0f / (1.0f + expf(-z));
    }
}

// ------------------------- launch -------------------------------------------
extern "C" void kernel_launch(void* const* d_in, const int* in_sizes, int n_in,
                              void* d_out, int out_size) {
    const float* x     = (const float*)d_in[0];
    const int*   step  = (const int*)  d_in[1];
    const float* roots = (const float*)d_in[2];
    const float* projW = (const float*)d_in[3];
    const float* gW    = (const float*)d_in[4];
    const float* gb    = (const float*)d_in[5];
    const float* eW    = (const float*)d_in[6];
    const float* ebias = (const float*)d_in[7];
    const float* gamma = (const float*)d_in[8];
    const float* beta  = (const float*)d_in[9];
    const float* hW    = (const float*)d_in[10];
    const float* hb    = (const float*)d_in[11];
    float* out = (float*)d_out;

    setup_kernel<<<240, DIMV>>>(roots, projW);
    cycle_kernel<<<NTOK, DIMV>>>(x, step);

    for (int L = 0; L < NDEPTH; L++) {
        gate_kernel<<<NTOK / 8, 256>>>(gW + (size_t)L * DIMV * NEXP,
                                       gb + (size_t)L * NEXP, L);
        dim3 gg(NTOK / MT, NEXP);
        moe_gemm_kernel<<<gg, 256>>>(eW + (size_t)L * NEXP * DIMV * DIMV, L);
        epi_kernel<<<NTOK / 8, 256>>>(ebias + (size_t)L * NEXP * DIMV, gamma, beta);
    }

    head_kernel<<<BB, 256>>>(hW, hb, out);
}